// round 12
// baseline (speedup 1.0000x reference)
#include <cuda_runtime.h>

// noiseRNN: h_t = tanh(W_ih x_t + b_ih + W_hh h_{t-1} + b_hh); carry h_t + 0.1*noise_t
// T=2048, B=256, I=64, H=128.
// R12: R10 base (128 blocks x 2 batches x 256 threads, W in regs 4j x 24k,
// f32x2 FMAs, SMEM partial reduce, depth-4 prefetch rings) + SOFTWARE PIPELINE
// of the two independent batch chains: each phase runs matvec of one batch
// concurrently with the reduce/tanh/z-update of the OTHER batch, so the serial
// tail hides under 192 cycles of FMA issue instead of being exposed.
//   Phase B(t): matvec zB->pB   || reduce pA -> zA(t+1)  (warps 0-3) + stage xA
//   Phase A(t): matvec zA->pA   || reduce pB -> zB(t+1)  (warps 4-7) + stage xB
// One __syncthreads per phase; buffers {pA,pB,zA,zB} have disjoint R/W sets per phase.

#define T_STEPS 2048
#define BATCH   256
#define IN_DIM  64
#define HID     128
#define KDIM    192           // HID + IN_DIM
#define STD_F   0.1f

#define NWARPS  8
#define KSLICE  24            // KDIM / NWARPS
#define THREADS 256
#define NP      4             // prefetch ring depth (T_STEPS % NP == 0)

__device__ __forceinline__ unsigned long long fma2(unsigned long long a,
                                                   unsigned long long b,
                                                   unsigned long long c) {
    unsigned long long d;
    asm("fma.rn.f32x2 %0, %1, %2, %3;" : "=l"(d) : "l"(a), "l"(b), "l"(c));
    return d;
}
__device__ __forceinline__ unsigned long long packf2(float lo, float hi) {
    return (unsigned long long)__float_as_uint(lo) |
           ((unsigned long long)__float_as_uint(hi) << 32);
}
__device__ __forceinline__ float lo_f(unsigned long long v) {
    return __uint_as_float((unsigned)v);
}
__device__ __forceinline__ float hi_f(unsigned long long v) {
    return __uint_as_float((unsigned)(v >> 32));
}
// tanh(s) = 1 - 2/(exp(2s)+1): 2 MUFU + 4 fp ops, ~1e-6 accuracy (validated).
__device__ __forceinline__ float fast_tanh(float s) {
    float e = __expf(2.0f * s);
    return 1.0f - __fdividef(2.0f, e + 1.0f);
}

__global__ void __launch_bounds__(THREADS, 1) noise_rnn_kernel(
    const float* __restrict__ x,         // [T,B,I]
    const float* __restrict__ w_ih,      // [H,I]
    const float* __restrict__ w_hh,      // [H,H]
    const float* __restrict__ b_ih,      // [H]
    const float* __restrict__ b_hh,      // [H]
    const float* __restrict__ noise,     // [T,B,H]
    const float* __restrict__ hidden_in, // [1,B,H]
    float* __restrict__ out,             // [T,B,H] (+ [1,B,H] h_last)
    int out_size)
{
    __shared__ __align__(16) float zA[KDIM];
    __shared__ __align__(16) float zB[KDIM];
    __shared__ __align__(16) float pA[NWARPS * HID];   // partials batch A (4 KB)
    __shared__ __align__(16) float pB[NWARPS * HID];   // partials batch B (4 KB)

    const int tid   = threadIdx.x;
    const int lane  = tid & 31;
    const int warp  = tid >> 5;
    const int bA    = blockIdx.x * 2;
    const int bB    = bA + 1;
    const int jbase = lane * 4;        // this thread's 4 output rows
    const int ks    = warp * KSLICE;   // this thread's k-slice start

    // roles: warps 0-3 reduce batch A; warps 4-7 reduce batch B (both phases
    // every thread also does the current phase's matvec).
    const bool redA = (tid < HID);
    const int  rj   = redA ? tid : (tid - HID);        // reduced output row
    const int  gb   = redA ? bA : bB;                  // reducer's batch
    const bool stA  = (tid >= HID) && (tid < HID + IN_DIM);  // stage x for A
    const bool stB  = (tid < IN_DIM);                        // stage x for B
    const bool isSt = stA || stB;

    // --- W_cat tile in registers, k-pair packed ---
    // W_cat[j][k] = k < HID ? w_hh[j][k] : w_ih[j][k-HID]
    unsigned long long wpk[4][12];
#pragma unroll
    for (int p = 0; p < 12; ++p) {
        const int k0 = ks + 2 * p;
        const int k1 = k0 + 1;
#pragma unroll
        for (int jj = 0; jj < 4; ++jj) {
            const int j = jbase + jj;
            const float lo = (k0 < HID) ? w_hh[j * HID + k0]
                                        : w_ih[j * IN_DIM + (k0 - HID)];
            const float hi = (k1 < HID) ? w_hh[j * HID + k1]
                                        : w_ih[j * IN_DIM + (k1 - HID)];
            wpk[jj][p] = packf2(lo, hi);
        }
    }

    const float bias_r = b_ih[rj] + b_hh[rj];
    const int   nb     = gb * HID + rj;                      // out/noise offset
    const int   xoff   = stA ? (bA * IN_DIM + (tid - HID))   // stager's x offset
                             : (bB * IN_DIM + tid);
    const int   zxi    = stA ? (tid - HID) : tid;            // x slot in z

    // --- init z(t=0) = [h0; x0] for both batches ---
    if (redA) zA[rj] = hidden_in[bA * HID + rj];
    else      zB[rj] = hidden_in[bB * HID + rj];
    if (stA)  zA[HID + zxi] = x[xoff];
    if (stB)  zB[HID + zxi] = x[xoff];
    __syncthreads();

    // --- prefetch rings ---
    float nzbuf[NP], xbuf[NP];
#pragma unroll
    for (int u = 0; u < NP; ++u) {
        nzbuf[u] = noise[u * (BATCH * HID) + nb];
        xbuf[u]  = (isSt && (u + 1) < T_STEPS)
                   ? x[(u + 1) * (BATCH * IN_DIM) + xoff] : 0.0f;
    }

    // matvec of one batch: 24 warp-uniform LDS.128 + 48 fma2, store 1 STS.128
    auto matvec = [&](const float* zsrc, float* pdst) {
        unsigned long long a0 = 0ull, a1 = 0ull, a2 = 0ull, a3 = 0ull;
        const ulonglong2* zq = reinterpret_cast<const ulonglong2*>(zsrc + ks);
#pragma unroll
        for (int q = 0; q < 6; ++q) {
            const ulonglong2 v = zq[q];
            a0 = fma2(wpk[0][2 * q], v.x, a0); a0 = fma2(wpk[0][2 * q + 1], v.y, a0);
            a1 = fma2(wpk[1][2 * q], v.x, a1); a1 = fma2(wpk[1][2 * q + 1], v.y, a1);
            a2 = fma2(wpk[2][2 * q], v.x, a2); a2 = fma2(wpk[2][2 * q + 1], v.y, a2);
            a3 = fma2(wpk[3][2 * q], v.x, a3); a3 = fma2(wpk[3][2 * q + 1], v.y, a3);
        }
        float4 p;
        p.x = lo_f(a0) + hi_f(a0);
        p.y = lo_f(a1) + hi_f(a1);
        p.z = lo_f(a2) + hi_f(a2);
        p.w = lo_f(a3) + hi_f(a3);
        *reinterpret_cast<float4*>(pdst + warp * HID + jbase) = p;
    };

    // reduce own batch for step tt from psrc; write z row + out; refill rings
    auto reduce_own = [&](const float* psrc, float* zdst, int tt, int u) {
        const float q0 = psrc[0 * HID + rj];
        const float q1 = psrc[1 * HID + rj];
        const float q2 = psrc[2 * HID + rj];
        const float q3 = psrc[3 * HID + rj];
        const float q4 = psrc[4 * HID + rj];
        const float q5 = psrc[5 * HID + rj];
        const float q6 = psrc[6 * HID + rj];
        const float q7 = psrc[7 * HID + rj];
        const float s = (((q0 + q1) + (q2 + q3)) + ((q4 + q5) + (q6 + q7))) + bias_r;

        const float hn = fast_tanh(s);
        out[tt * (BATCH * HID) + nb] = hn;
        const float zn = hn + STD_F * nzbuf[u];
        zdst[rj] = zn;
        if ((tt + NP) < T_STEPS)
            nzbuf[u] = noise[(tt + NP) * (BATCH * HID) + nb];
        if (tt == T_STEPS - 1 && out_size > T_STEPS * BATCH * HID)
            out[T_STEPS * (BATCH * HID) + nb] = zn;          // h_last
    };

    // --- bootstrap: matvec A(0) ---
    matvec(zA, pA);
    __syncthreads();

    for (int t = 0; t < T_STEPS; t += NP) {
#pragma unroll
        for (int u = 0; u < NP; ++u) {
            const int tt = t + u;

            // ---- Phase B: matvec B(tt) || reduce A(tt) + stage xA(tt+1) ----
            matvec(zB, pB);
            if (redA) reduce_own(pA, zA, tt, u);
            if (stA) {
                if ((tt + 1) < T_STEPS) zA[HID + zxi] = xbuf[u];
                if ((tt + NP + 1) < T_STEPS)
                    xbuf[u] = x[(tt + NP + 1) * (BATCH * IN_DIM) + xoff];
            }
            __syncthreads();

            // ---- Phase A: matvec A(tt+1) || reduce B(tt) + stage xB(tt+1) ----
            if ((tt + 1) < T_STEPS) matvec(zA, pA);
            if (!redA) reduce_own(pB, zB, tt, u);
            if (stB) {
                if ((tt + 1) < T_STEPS) zB[HID + zxi] = xbuf[u];
                if ((tt + NP + 1) < T_STEPS)
                    xbuf[u] = x[(tt + NP + 1) * (BATCH * IN_DIM) + xoff];
            }
            __syncthreads();
        }
    }
}

extern "C" void kernel_launch(void* const* d_in, const int* in_sizes, int n_in,
                              void* d_out, int out_size) {
    const float* x         = (const float*)d_in[0];
    const float* w_ih      = (const float*)d_in[1];
    const float* w_hh      = (const float*)d_in[2];
    const float* b_ih      = (const float*)d_in[3];
    const float* b_hh      = (const float*)d_in[4];
    const float* noise     = (const float*)d_in[5];
    const float* hidden_in = (const float*)d_in[6];
    float* out = (float*)d_out;

    noise_rnn_kernel<<<BATCH / 2, THREADS>>>(x, w_ih, w_hh, b_ih, b_hh,
                                             noise, hidden_in, out, out_size);
}

// round 13
// speedup vs baseline: 1.2955x; 1.2955x over previous
#include <cuda_runtime.h>

// noiseRNN: h_t = tanh(W_ih x_t + b_ih + W_hh h_{t-1} + b_hh); carry h_t + 0.1*noise_t
// T=2048, B=256, I=64, H=128.
// R13: intra-warp reduction, ONE barrier per step.
// 128 blocks x 256 threads, 2 batches/block. Warp w owns output rows
// j in [16w,16w+16) for BOTH batches. Lane l: j = 16w + (l&15), k-half = l>>4
// (k in [96*half, 96*half+96)). Both lane-groups matvec both batches over their
// k-half (96 fma2/lane/step, weights shared across batches), then ONE
// shfl_xor(16) completes each dot product. half=0 lanes finalize (j,batchA),
// half=1 lanes finalize (j,batchB): tanh + out + z-write. z is double-buffered
// (read cur / write nxt) so a single __syncthreads per step suffices.
// k-half-1 z region lives at word offset 112 (== 16 mod 32) so the two 16-lane
// broadcast groups always hit disjoint bank sets. Depth-4 prefetch rings for
// noise/x (proven in R10) and fast tanh (validated 2.6e-7).

#define T_STEPS 2048
#define BATCH   256
#define IN_DIM  64
#define HID     128
#define STD_F   0.1f
#define THREADS 256
#define NP      4      // prefetch ring depth (T_STEPS % NP == 0)
#define ZSZ     208    // z layout: region0 [0,96) = z[0..96); region1 at [112,208) = z[96..192)

__device__ __forceinline__ unsigned long long fma2(unsigned long long a,
                                                   unsigned long long b,
                                                   unsigned long long c) {
    unsigned long long d;
    asm("fma.rn.f32x2 %0, %1, %2, %3;" : "=l"(d) : "l"(a), "l"(b), "l"(c));
    return d;
}
__device__ __forceinline__ unsigned long long packf2(float lo, float hi) {
    return (unsigned long long)__float_as_uint(lo) |
           ((unsigned long long)__float_as_uint(hi) << 32);
}
__device__ __forceinline__ float lo_f(unsigned long long v) {
    return __uint_as_float((unsigned)v);
}
__device__ __forceinline__ float hi_f(unsigned long long v) {
    return __uint_as_float((unsigned)(v >> 32));
}
// tanh(s) = 1 - 2/(exp(2s)+1): 2 MUFU + 4 fp ops, ~1e-6 accuracy (validated).
__device__ __forceinline__ float fast_tanh(float s) {
    float e = __expf(2.0f * s);
    return 1.0f - __fdividef(2.0f, e + 1.0f);
}

__global__ void __launch_bounds__(THREADS, 1) noise_rnn_kernel(
    const float* __restrict__ x,         // [T,B,I]
    const float* __restrict__ w_ih,      // [H,I]
    const float* __restrict__ w_hh,      // [H,H]
    const float* __restrict__ b_ih,      // [H]
    const float* __restrict__ b_hh,      // [H]
    const float* __restrict__ noise,     // [T,B,H]
    const float* __restrict__ hidden_in, // [1,B,H]
    float* __restrict__ out,             // [T,B,H] (+ [1,B,H] h_last)
    int out_size)
{
    // [buffer][batch][ZSZ]: region0 words [0,96) = z[0..96),
    //                       region1 words [112,208) = z[96..192) (h rows 96..127 then x 0..63)
    __shared__ __align__(16) float zbuf[2][2][ZSZ];

    const int tid  = threadIdx.x;
    const int lane = tid & 31;
    const int warp = tid >> 5;
    const int bA   = blockIdx.x * 2;

    const int  half = lane >> 4;              // k-half: 0 -> [0,96), 1 -> [96,192)
    const int  j    = warp * 16 + (lane & 15);// this lane's output row
    const int  myb  = bA + half;              // batch this lane finalizes
    const int  zw   = (j < 96) ? j : (112 + j - 96);   // z write slot for row j

    // x-stager role: tid<128 stages x; tid>>6 selects batch, tid&63 the index
    const bool isX    = (tid < 128);
    const int  xbatch = (tid >> 6) & 1;
    const int  xi     = tid & 63;
    const int  xg     = (bA + xbatch) * IN_DIM + xi;

    // --- weights: lane's row j over its k-half, k-pair packed (shared by both batches) ---
    // W_cat[j][k] = k < HID ? w_hh[j][k] : w_ih[j][k-HID]
    unsigned long long wpk[48];
    {
        const float* whr = w_hh + j * HID;
        const float* wir = w_ih + j * IN_DIM;
#pragma unroll
        for (int p = 0; p < 48; ++p) {
            const int k0 = 96 * half + 2 * p;
            const int k1 = k0 + 1;
            const float lo = (k0 < HID) ? whr[k0] : wir[k0 - HID];
            const float hi = (k1 < HID) ? whr[k1] : wir[k1 - HID];
            wpk[p] = packf2(lo, hi);
        }
    }

    const float bias = b_ih[j] + b_hh[j];
    const int   nb   = myb * HID + j;         // out/noise offset for this lane

    // --- init buffer 0: z(0) = [h0; x0] for both batches ---
    zbuf[0][half][zw] = hidden_in[nb];        // lane's (j, batch=half) h0 row
    if (isX) zbuf[0][xbatch][144 + xi] = x[xg];
    __syncthreads();

    // --- depth-NP prefetch rings ---
    float nzr[NP], xr[NP];
#pragma unroll
    for (int u = 0; u < NP; ++u) {
        nzr[u] = noise[u * (BATCH * HID) + nb];
        xr[u]  = (isX && (u + 1) < T_STEPS)
                 ? x[(u + 1) * (BATCH * IN_DIM) + xg] : 0.0f;
    }

    for (int t = 0; t < T_STEPS; t += NP) {
#pragma unroll
        for (int u = 0; u < NP; ++u) {
            const int tt  = t + u;
            const int cur = tt & 1;
            const int nxt = cur ^ 1;

            // --- matvec over this lane's k-half, both batches: 48 LDS.128 + 96 fma2 ---
            const ulonglong2* pa =
                reinterpret_cast<const ulonglong2*>(&zbuf[cur][0][half * 112]);
            const ulonglong2* pb =
                reinterpret_cast<const ulonglong2*>(&zbuf[cur][1][half * 112]);
            unsigned long long a0 = 0ull, a1 = 0ull, a2 = 0ull, a3 = 0ull;
            unsigned long long c0 = 0ull, c1 = 0ull, c2 = 0ull, c3 = 0ull;
#pragma unroll
            for (int i = 0; i < 24; ++i) {
                const ulonglong2 va = pa[i];   // 2-addr broadcast, disjoint banks
                const ulonglong2 vb = pb[i];
                if (i & 1) {
                    a1 = fma2(wpk[2 * i],     va.x, a1);
                    a3 = fma2(wpk[2 * i + 1], va.y, a3);
                    c1 = fma2(wpk[2 * i],     vb.x, c1);
                    c3 = fma2(wpk[2 * i + 1], vb.y, c3);
                } else {
                    a0 = fma2(wpk[2 * i],     va.x, a0);
                    a2 = fma2(wpk[2 * i + 1], va.y, a2);
                    c0 = fma2(wpk[2 * i],     vb.x, c0);
                    c2 = fma2(wpk[2 * i + 1], vb.y, c2);
                }
            }
            const float sA = ((lo_f(a0) + hi_f(a0)) + (lo_f(a1) + hi_f(a1)))
                           + ((lo_f(a2) + hi_f(a2)) + (lo_f(a3) + hi_f(a3)));
            const float sB = ((lo_f(c0) + hi_f(c0)) + (lo_f(c1) + hi_f(c1)))
                           + ((lo_f(c2) + hi_f(c2)) + (lo_f(c3) + hi_f(c3)));

            // --- intra-warp reduce: partner lane (l^16) holds the other k-half, same j ---
            const float fullA = sA + __shfl_xor_sync(0xFFFFFFFFu, sA, 16);
            const float fullB = sB + __shfl_xor_sync(0xFFFFFFFFu, sB, 16);
            const float s = (half ? fullB : fullA) + bias;

            // --- epilogue: one (j, batch) per lane ---
            const float hn = fast_tanh(s);
            out[tt * (BATCH * HID) + nb] = hn;

            const float zn = hn + STD_F * nzr[u];   // noisy carried state
            if ((tt + NP) < T_STEPS)
                nzr[u] = noise[(tt + NP) * (BATCH * HID) + nb];
            zbuf[nxt][half][zw] = zn;

            if (tt == T_STEPS - 1 && out_size > T_STEPS * BATCH * HID)
                out[T_STEPS * (BATCH * HID) + nb] = zn;   // h_last

            if (isX && (tt + 1) < T_STEPS) {
                zbuf[nxt][xbatch][144 + xi] = xr[u];      // stage next x
                if ((tt + NP + 1) < T_STEPS)
                    xr[u] = x[(tt + NP + 1) * (BATCH * IN_DIM) + xg];
            }

            __syncthreads();   // single per-step barrier: nxt-buffer handoff
        }
    }
}

extern "C" void kernel_launch(void* const* d_in, const int* in_sizes, int n_in,
                              void* d_out, int out_size) {
    const float* x         = (const float*)d_in[0];
    const float* w_ih      = (const float*)d_in[1];
    const float* w_hh      = (const float*)d_in[2];
    const float* b_ih      = (const float*)d_in[3];
    const float* b_hh      = (const float*)d_in[4];
    const float* noise     = (const float*)d_in[5];
    const float* hidden_in = (const float*)d_in[6];
    float* out = (float*)d_out;

    noise_rnn_kernel<<<BATCH / 2, THREADS>>>(x, w_ih, w_hh, b_ih, b_hh,
                                             noise, hidden_in, out, out_size);
}

// round 14
// speedup vs baseline: 1.6694x; 1.2887x over previous
#include <cuda_runtime.h>

// noiseRNN: h_t = tanh(W_ih x_t + b_ih + W_hh h_{t-1} + b_hh); carry h_t + 0.1*noise_t
// T=2048, B=256, I=64, H=128.
// R14 = R10 structure scaled to 12 warps (3/SMSP) to hide the serial tail:
// 128 blocks x 2 batches x 384 threads. Warp w owns k-slice [16w,16w+16);
// thread: 4 j-rows x 16 k x 2 batches (wpk 4x8 packed f32x2 = 64 regs,
// 8 LDS.128/step). SMEM partial reduce (12 partials), depth-4 prefetch rings
// (noise: reducers tid<256; x: dedicated stagers tid 256..383), fast tanh.

#define T_STEPS 2048
#define BATCH   256
#define IN_DIM  64
#define HID     128
#define KDIM    192           // HID + IN_DIM
#define STD_F   0.1f

#define NWARPS  12
#define KSLICE  16            // KDIM / NWARPS
#define THREADS 384
#define NP      4             // prefetch ring depth (T_STEPS % NP == 0)

__device__ __forceinline__ unsigned long long fma2(unsigned long long a,
                                                   unsigned long long b,
                                                   unsigned long long c) {
    unsigned long long d;
    asm("fma.rn.f32x2 %0, %1, %2, %3;" : "=l"(d) : "l"(a), "l"(b), "l"(c));
    return d;
}
__device__ __forceinline__ unsigned long long packf2(float lo, float hi) {
    return (unsigned long long)__float_as_uint(lo) |
           ((unsigned long long)__float_as_uint(hi) << 32);
}
__device__ __forceinline__ float lo_f(unsigned long long v) {
    return __uint_as_float((unsigned)v);
}
__device__ __forceinline__ float hi_f(unsigned long long v) {
    return __uint_as_float((unsigned)(v >> 32));
}
// tanh(s) = 1 - 2/(exp(2s)+1): 2 MUFU + 4 fp ops, ~1e-6 accuracy (validated).
__device__ __forceinline__ float fast_tanh(float s) {
    float e = __expf(2.0f * s);
    return 1.0f - __fdividef(2.0f, e + 1.0f);
}

__global__ void __launch_bounds__(THREADS, 1) noise_rnn_kernel(
    const float* __restrict__ x,         // [T,B,I]
    const float* __restrict__ w_ih,      // [H,I]
    const float* __restrict__ w_hh,      // [H,H]
    const float* __restrict__ b_ih,      // [H]
    const float* __restrict__ b_hh,      // [H]
    const float* __restrict__ noise,     // [T,B,H]
    const float* __restrict__ hidden_in, // [1,B,H]
    float* __restrict__ out,             // [T,B,H] (+ [1,B,H] h_last)
    int out_size)
{
    __shared__ __align__(16) float zA[KDIM];
    __shared__ __align__(16) float zB[KDIM];
    __shared__ __align__(16) float psh[NWARPS * 256];   // [warp][j*2 + b] 12 KB

    const int tid   = threadIdx.x;
    const int lane  = tid & 31;
    const int warp  = tid >> 5;
    const int b0    = blockIdx.x * 2;
    const int jbase = lane * 4;        // this thread's 4 output rows
    const int ks    = warp * KSLICE;   // this thread's k-slice start

    // reducer role (tid < 256): output (j = tid>>1, b = tid&1)
    const bool isRed = (tid < 256);
    const int rj = (tid >> 1) & 127;
    const int rb = tid & 1;
    const int gb = b0 + rb;

    // x-stager role (tid in [256,384)): xi<128 -> batch xi>>6, index xi&63
    const bool isXst = (tid >= 256);
    const int  xi    = tid - 256;
    const int  xbat  = (xi >> 6) & 1;
    const int  xidx  = xi & 63;
    const int  xg    = (b0 + xbat) * IN_DIM + xidx;
    float* const zx  = xbat ? zB : zA;

    // --- W_cat tile in registers, k-pair packed ---
    // W_cat[j][k] = k < HID ? w_hh[j][k] : w_ih[j][k-HID]
    unsigned long long wpk[4][8];
#pragma unroll
    for (int p = 0; p < 8; ++p) {
        const int k0 = ks + 2 * p;
        const int k1 = k0 + 1;
#pragma unroll
        for (int jj = 0; jj < 4; ++jj) {
            const int j = jbase + jj;
            const float lo = (k0 < HID) ? w_hh[j * HID + k0]
                                        : w_ih[j * IN_DIM + (k0 - HID)];
            const float hi = (k1 < HID) ? w_hh[j * HID + k1]
                                        : w_ih[j * IN_DIM + (k1 - HID)];
            wpk[jj][p] = packf2(lo, hi);
        }
    }

    const float bias_r = b_ih[rj] + b_hh[rj];

    // --- init z(t=0) = [h0; x0] ---
    if (isRed) {
        float* zp = rb ? zB : zA;
        zp[rj] = hidden_in[gb * HID + rj];
    }
    if (isXst) zx[HID + xidx] = x[xg];
    __syncthreads();

    const int nb = gb * HID + rj;     // reducers' out/noise offset

    // --- depth-NP prefetch rings ---
    float nzbuf[NP], xbuf[NP];
#pragma unroll
    for (int u = 0; u < NP; ++u) {
        nzbuf[u] = isRed ? noise[u * (BATCH * HID) + nb] : 0.0f;
        xbuf[u]  = (isXst && (u + 1) < T_STEPS)
                   ? x[(u + 1) * (BATCH * IN_DIM) + xg] : 0.0f;
    }

    for (int t = 0; t < T_STEPS; t += NP) {
#pragma unroll
        for (int u = 0; u < NP; ++u) {
            const int tt = t + u;

            const float nz = nzbuf[u];
            const float xn = xbuf[u];
            if (isRed && (tt + NP) < T_STEPS)
                nzbuf[u] = noise[(tt + NP) * (BATCH * HID) + nb];
            if (isXst && (tt + NP + 1) < T_STEPS)
                xbuf[u] = x[(tt + NP + 1) * (BATCH * IN_DIM) + xg];

            // --- matvec partials: 4 j x 16 k x 2 batches (8 LDS.128, 32 fma2) ---
            unsigned long long accA[4] = {0ull, 0ull, 0ull, 0ull};
            unsigned long long accB[4] = {0ull, 0ull, 0ull, 0ull};
            const ulonglong2* zAp = reinterpret_cast<const ulonglong2*>(zA + ks);
            const ulonglong2* zBp = reinterpret_cast<const ulonglong2*>(zB + ks);
#pragma unroll
            for (int q = 0; q < 4; ++q) {
                const ulonglong2 va = zAp[q];   // warp-uniform broadcast LDS.128
                const ulonglong2 vb = zBp[q];
#pragma unroll
                for (int jj = 0; jj < 4; ++jj) {
                    accA[jj] = fma2(wpk[jj][2 * q],     va.x, accA[jj]);
                    accA[jj] = fma2(wpk[jj][2 * q + 1], va.y, accA[jj]);
                    accB[jj] = fma2(wpk[jj][2 * q],     vb.x, accB[jj]);
                    accB[jj] = fma2(wpk[jj][2 * q + 1], vb.y, accB[jj]);
                }
            }

            // --- store partials (horizontal add of f32x2 halves) ---
            {
                float4 p0, p1;
                p0.x = lo_f(accA[0]) + hi_f(accA[0]);
                p0.y = lo_f(accB[0]) + hi_f(accB[0]);
                p0.z = lo_f(accA[1]) + hi_f(accA[1]);
                p0.w = lo_f(accB[1]) + hi_f(accB[1]);
                p1.x = lo_f(accA[2]) + hi_f(accA[2]);
                p1.y = lo_f(accB[2]) + hi_f(accB[2]);
                p1.z = lo_f(accA[3]) + hi_f(accA[3]);
                p1.w = lo_f(accB[3]) + hi_f(accB[3]);
                float4* pp = reinterpret_cast<float4*>(psh + warp * 256 + jbase * 2);
                pp[0] = p0;
                pp[1] = p1;
            }
            __syncthreads();

            // --- reduce: thread tid<256 owns output (rj, rb); index j*2+b == tid ---
            if (isRed) {
                float s = bias_r;
                float acc0 = 0.0f, acc1 = 0.0f, acc2 = 0.0f, acc3 = 0.0f;
#pragma unroll
                for (int w = 0; w < NWARPS; w += 4) {
                    acc0 += psh[(w + 0) * 256 + tid];
                    acc1 += psh[(w + 1) * 256 + tid];
                    acc2 += psh[(w + 2) * 256 + tid];
                    acc3 += psh[(w + 3) * 256 + tid];
                }
                s += (acc0 + acc1) + (acc2 + acc3);

                const float hn = fast_tanh(s);
                out[tt * (BATCH * HID) + nb] = hn;

                const float zn = hn + STD_F * nz;    // noisy carried state
                float* zp = rb ? zB : zA;
                zp[rj] = zn;

                if (tt == T_STEPS - 1 && out_size > T_STEPS * BATCH * HID)
                    out[T_STEPS * (BATCH * HID) + nb] = zn;   // h_last
            }
            if (isXst && (tt + 1) < T_STEPS)
                zx[HID + xidx] = xn;                 // stage next x (parallel role)

            __syncthreads();
        }
    }
}

extern "C" void kernel_launch(void* const* d_in, const int* in_sizes, int n_in,
                              void* d_out, int out_size) {
    const float* x         = (const float*)d_in[0];
    const float* w_ih      = (const float*)d_in[1];
    const float* w_hh      = (const float*)d_in[2];
    const float* b_ih      = (const float*)d_in[3];
    const float* b_hh      = (const float*)d_in[4];
    const float* noise     = (const float*)d_in[5];
    const float* hidden_in = (const float*)d_in[6];
    float* out = (float*)d_out;

    noise_rnn_kernel<<<BATCH / 2, THREADS>>>(x, w_ih, w_hh, b_ih, b_hh,
                                             noise, hidden_in, out, out_size);
}

// round 15
// speedup vs baseline: 1.8869x; 1.1303x over previous
#include <cuda_runtime.h>

// noiseRNN: h_t = tanh(W_ih x_t + b_ih + W_hh h_{t-1} + b_hh); carry h_t + 0.1*noise_t
// T=2048, B=256, I=64, H=128.
// R15: TWO independent barrier domains per CTA via named barriers.
// 128 blocks x 256 threads; group g = tid>>7 (128 threads, warps 4g..4g+3) owns
// batch 2*blockIdx.x+g end-to-end with its own bar.sync(1+g, 128). Groups share
// no data; SMSP issue contention anti-phases them so one group's serial
// reduce/tanh/barrier tail hides under the other group's FMA stream.
// Within a group: warp w_in_g owns k-slice [48*w,48*w+48); thread: 4 j-rows x
// 48 k in regs (96 packed f32x2), 12 warp-uniform LDS.128/step, 4-partial SMEM
// reduce. Depth-4 prefetch rings (noise + x), fast tanh (validated 2.6e-7).

#define T_STEPS 2048
#define BATCH   256
#define IN_DIM  64
#define HID     128
#define KDIM    192           // HID + IN_DIM
#define STD_F   0.1f
#define THREADS 256
#define NP      4             // prefetch ring depth (T_STEPS % NP == 0)

__device__ __forceinline__ unsigned long long fma2(unsigned long long a,
                                                   unsigned long long b,
                                                   unsigned long long c) {
    unsigned long long d;
    asm("fma.rn.f32x2 %0, %1, %2, %3;" : "=l"(d) : "l"(a), "l"(b), "l"(c));
    return d;
}
__device__ __forceinline__ unsigned long long packf2(float lo, float hi) {
    return (unsigned long long)__float_as_uint(lo) |
           ((unsigned long long)__float_as_uint(hi) << 32);
}
__device__ __forceinline__ float lo_f(unsigned long long v) {
    return __uint_as_float((unsigned)v);
}
__device__ __forceinline__ float hi_f(unsigned long long v) {
    return __uint_as_float((unsigned)(v >> 32));
}
// tanh(s) = 1 - 2/(exp(2s)+1): 2 MUFU + 4 fp ops, ~1e-6 accuracy (validated).
__device__ __forceinline__ float fast_tanh(float s) {
    float e = __expf(2.0f * s);
    return 1.0f - __fdividef(2.0f, e + 1.0f);
}
// group-scoped barrier: all 128 threads of group execute it
__device__ __forceinline__ void group_bar(int gid) {
    asm volatile("bar.sync %0, %1;" :: "r"(gid + 1), "r"(128) : "memory");
}

__global__ void __launch_bounds__(THREADS, 1) noise_rnn_kernel(
    const float* __restrict__ x,         // [T,B,I]
    const float* __restrict__ w_ih,      // [H,I]
    const float* __restrict__ w_hh,      // [H,H]
    const float* __restrict__ b_ih,      // [H]
    const float* __restrict__ b_hh,      // [H]
    const float* __restrict__ noise,     // [T,B,H]
    const float* __restrict__ hidden_in, // [1,B,H]
    float* __restrict__ out,             // [T,B,H] (+ [1,B,H] h_last)
    int out_size)
{
    __shared__ __align__(16) float zsh[2][KDIM];        // per-group z = [h; x_t]
    __shared__ __align__(16) float psh[2][4 * HID];     // per-group partials (2 KB each)

    const int tid  = threadIdx.x;
    const int lane = tid & 31;
    const int gid  = tid >> 7;          // group 0/1
    const int gtid = tid & 127;         // thread id within group
    const int wg   = gtid >> 5;         // warp within group (0..3)
    const int b    = blockIdx.x * 2 + gid;   // this group's batch

    const int jbase = lane * 4;         // matvec: this thread's 4 output rows
    const int ks    = wg * 48;          // k-slice start (48 wide)
    const int rj    = gtid;             // reduce: this thread's output row

    float* const z  = zsh[gid];
    float* const ps = psh[gid];

    // --- W_cat tile in registers, k-pair packed ---
    // W_cat[j][k] = k < HID ? w_hh[j][k] : w_ih[j][k-HID]
    unsigned long long wpk[4][24];
#pragma unroll
    for (int p = 0; p < 24; ++p) {
        const int k0 = ks + 2 * p;
        const int k1 = k0 + 1;
#pragma unroll
        for (int jj = 0; jj < 4; ++jj) {
            const int j = jbase + jj;
            const float lo = (k0 < HID) ? w_hh[j * HID + k0]
                                        : w_ih[j * IN_DIM + (k0 - HID)];
            const float hi = (k1 < HID) ? w_hh[j * HID + k1]
                                        : w_ih[j * IN_DIM + (k1 - HID)];
            wpk[jj][p] = packf2(lo, hi);
        }
    }

    const float bias_r = b_ih[rj] + b_hh[rj];
    const bool  stX    = (rj < IN_DIM);     // this thread also stages x[rj]

    // --- init z(t=0) = [h0; x0] ---
    z[rj] = hidden_in[b * HID + rj];
    if (stX) z[HID + rj] = x[b * IN_DIM + rj];
    __syncthreads();   // one global barrier; afterwards groups are independent

    const int nb = b * HID + rj;        // out/noise offset
    const int xg = b * IN_DIM + rj;     // x offset (stX threads)

    // --- depth-NP prefetch rings ---
    float nzr[NP], xr[NP];
#pragma unroll
    for (int u = 0; u < NP; ++u) {
        nzr[u] = noise[u * (BATCH * HID) + nb];
        xr[u]  = (stX && (u + 1) < T_STEPS)
                 ? x[(u + 1) * (BATCH * IN_DIM) + xg] : 0.0f;
    }

    for (int t = 0; t < T_STEPS; t += NP) {
#pragma unroll
        for (int u = 0; u < NP; ++u) {
            const int tt = t + u;

            const float nz = nzr[u];
            const float xn = xr[u];
            if ((tt + NP) < T_STEPS)
                nzr[u] = noise[(tt + NP) * (BATCH * HID) + nb];
            if (stX && (tt + NP + 1) < T_STEPS)
                xr[u] = x[(tt + NP + 1) * (BATCH * IN_DIM) + xg];

            // --- matvec partials: 4 j-rows x 48 k (12 LDS.128, 96 fma2) ---
            unsigned long long a0 = 0ull, a1 = 0ull, a2 = 0ull, a3 = 0ull;
            const ulonglong2* zq = reinterpret_cast<const ulonglong2*>(z + ks);
#pragma unroll
            for (int q = 0; q < 12; ++q) {
                const ulonglong2 v = zq[q];   // warp-uniform broadcast LDS.128
                a0 = fma2(wpk[0][2 * q], v.x, a0); a0 = fma2(wpk[0][2 * q + 1], v.y, a0);
                a1 = fma2(wpk[1][2 * q], v.x, a1); a1 = fma2(wpk[1][2 * q + 1], v.y, a1);
                a2 = fma2(wpk[2][2 * q], v.x, a2); a2 = fma2(wpk[2][2 * q + 1], v.y, a2);
                a3 = fma2(wpk[3][2 * q], v.x, a3); a3 = fma2(wpk[3][2 * q + 1], v.y, a3);
            }
            {
                float4 p;
                p.x = lo_f(a0) + hi_f(a0);
                p.y = lo_f(a1) + hi_f(a1);
                p.z = lo_f(a2) + hi_f(a2);
                p.w = lo_f(a3) + hi_f(a3);
                *reinterpret_cast<float4*>(ps + wg * HID + jbase) = p;
            }
            group_bar(gid);

            // --- reduce: thread rj owns output row rj (4 partials, depth-2 tree) ---
            const float q0 = ps[0 * HID + rj];
            const float q1 = ps[1 * HID + rj];
            const float q2 = ps[2 * HID + rj];
            const float q3 = ps[3 * HID + rj];
            const float s  = ((q0 + q1) + (q2 + q3)) + bias_r;

            const float hn = fast_tanh(s);
            out[tt * (BATCH * HID) + nb] = hn;

            const float zn = hn + STD_F * nz;    // noisy carried state
            z[rj] = zn;
            if (stX && (tt + 1) < T_STEPS)
                z[HID + rj] = xn;                // stage next x

            if (tt == T_STEPS - 1 && out_size > T_STEPS * BATCH * HID)
                out[T_STEPS * (BATCH * HID) + nb] = zn;   // h_last

            group_bar(gid);
        }
    }
}

extern "C" void kernel_launch(void* const* d_in, const int* in_sizes, int n_in,
                              void* d_out, int out_size) {
    const float* x         = (const float*)d_in[0];
    const float* w_ih      = (const float*)d_in[1];
    const float* w_hh      = (const float*)d_in[2];
    const float* b_ih      = (const float*)d_in[3];
    const float* b_hh      = (const float*)d_in[4];
    const float* noise     = (const float*)d_in[5];
    const float* hidden_in = (const float*)d_in[6];
    float* out = (float*)d_out;

    noise_rnn_kernel<<<BATCH / 2, THREADS>>>(x, w_ih, w_hh, b_ih, b_hh,
                                             noise, hidden_in, out, out_size);
}

// round 16
// speedup vs baseline: 1.9618x; 1.0397x over previous
#include <cuda_runtime.h>

// noiseRNN: h_t = tanh(W_ih x_t + b_ih + W_hh h_{t-1} + b_hh); carry h_t + 0.1*noise_t
// T=2048, B=256, I=64, H=128.
// R16 = R15 (two independent named-barrier groups per CTA, each owning one
// batch: 4 warps, thread = 4 j-rows x 48 k in regs, 12 warp-uniform LDS.128,
// 4-partial SMEM reduce, depth-4 prefetch rings, fast tanh) + a deterministic
// ~384-cycle startup skew for group 1 so the groups run anti-phased: one
// group's FMA-heavy matvec overlaps the other group's reduce/tanh/barrier tail
// on every SMSP, keeping the FMA pipe fed continuously.

#define T_STEPS 2048
#define BATCH   256
#define IN_DIM  64
#define HID     128
#define KDIM    192           // HID + IN_DIM
#define STD_F   0.1f
#define THREADS 256
#define NP      4             // prefetch ring depth (T_STEPS % NP == 0)

__device__ __forceinline__ unsigned long long fma2(unsigned long long a,
                                                   unsigned long long b,
                                                   unsigned long long c) {
    unsigned long long d;
    asm("fma.rn.f32x2 %0, %1, %2, %3;" : "=l"(d) : "l"(a), "l"(b), "l"(c));
    return d;
}
__device__ __forceinline__ unsigned long long packf2(float lo, float hi) {
    return (unsigned long long)__float_as_uint(lo) |
           ((unsigned long long)__float_as_uint(hi) << 32);
}
__device__ __forceinline__ float lo_f(unsigned long long v) {
    return __uint_as_float((unsigned)v);
}
__device__ __forceinline__ float hi_f(unsigned long long v) {
    return __uint_as_float((unsigned)(v >> 32));
}
// tanh(s) = 1 - 2/(exp(2s)+1): 2 MUFU + 4 fp ops, ~1e-6 accuracy (validated).
__device__ __forceinline__ float fast_tanh(float s) {
    float e = __expf(2.0f * s);
    return 1.0f - __fdividef(2.0f, e + 1.0f);
}
// group-scoped barrier: all 128 threads of group execute it
__device__ __forceinline__ void group_bar(int gid) {
    asm volatile("bar.sync %0, %1;" :: "r"(gid + 1), "r"(128) : "memory");
}

__global__ void __launch_bounds__(THREADS, 1) noise_rnn_kernel(
    const float* __restrict__ x,         // [T,B,I]
    const float* __restrict__ w_ih,      // [H,I]
    const float* __restrict__ w_hh,      // [H,H]
    const float* __restrict__ b_ih,      // [H]
    const float* __restrict__ b_hh,      // [H]
    const float* __restrict__ noise,     // [T,B,H]
    const float* __restrict__ hidden_in, // [1,B,H]
    float* __restrict__ out,             // [T,B,H] (+ [1,B,H] h_last)
    int out_size)
{
    __shared__ __align__(16) float zsh[2][KDIM];        // per-group z = [h; x_t]
    __shared__ __align__(16) float psh[2][4 * HID];     // per-group partials

    const int tid  = threadIdx.x;
    const int lane = tid & 31;
    const int gid  = tid >> 7;          // group 0/1
    const int gtid = tid & 127;         // thread id within group
    const int wg   = gtid >> 5;         // warp within group (0..3)
    const int b    = blockIdx.x * 2 + gid;   // this group's batch

    const int jbase = lane * 4;         // matvec: this thread's 4 output rows
    const int ks    = wg * 48;          // k-slice start (48 wide)
    const int rj    = gtid;             // reduce: this thread's output row

    float* const z  = zsh[gid];
    float* const ps = psh[gid];

    // --- W_cat tile in registers, k-pair packed ---
    // W_cat[j][k] = k < HID ? w_hh[j][k] : w_ih[j][k-HID]
    unsigned long long wpk[4][24];
#pragma unroll
    for (int p = 0; p < 24; ++p) {
        const int k0 = ks + 2 * p;
        const int k1 = k0 + 1;
#pragma unroll
        for (int jj = 0; jj < 4; ++jj) {
            const int j = jbase + jj;
            const float lo = (k0 < HID) ? w_hh[j * HID + k0]
                                        : w_ih[j * IN_DIM + (k0 - HID)];
            const float hi = (k1 < HID) ? w_hh[j * HID + k1]
                                        : w_ih[j * IN_DIM + (k1 - HID)];
            wpk[jj][p] = packf2(lo, hi);
        }
    }

    const float bias_r = b_ih[rj] + b_hh[rj];
    const bool  stX    = (rj < IN_DIM);     // this thread also stages x[rj]

    // --- init z(t=0) = [h0; x0] ---
    z[rj] = hidden_in[b * HID + rj];
    if (stX) z[HID + rj] = x[b * IN_DIM + rj];
    __syncthreads();   // one global barrier; afterwards groups are independent

    // --- anti-phase skew: group 1 burns ~384 cycles (96 dependent fma2) ---
    if (gid == 1) {
        unsigned long long d = wpk[0][0];
#pragma unroll
        for (int i = 0; i < 96; ++i)
            d = fma2(d, wpk[i & 3][i % 24], d);   // serial chain, lat 4 each
        if (lo_f(d) == 1.2345e-30f)               // never true; defeats DCE
            z[rj] = hi_f(d);
    }

    const int nb = b * HID + rj;        // out/noise offset
    const int xg = b * IN_DIM + rj;     // x offset (stX threads)

    // --- depth-NP prefetch rings ---
    float nzr[NP], xr[NP];
#pragma unroll
    for (int u = 0; u < NP; ++u) {
        nzr[u] = noise[u * (BATCH * HID) + nb];
        xr[u]  = (stX && (u + 1) < T_STEPS)
                 ? x[(u + 1) * (BATCH * IN_DIM) + xg] : 0.0f;
    }

    for (int t = 0; t < T_STEPS; t += NP) {
#pragma unroll
        for (int u = 0; u < NP; ++u) {
            const int tt = t + u;

            const float nz = nzr[u];
            const float xn = xr[u];
            if ((tt + NP) < T_STEPS)
                nzr[u] = noise[(tt + NP) * (BATCH * HID) + nb];
            if (stX && (tt + NP + 1) < T_STEPS)
                xr[u] = x[(tt + NP + 1) * (BATCH * IN_DIM) + xg];

            // --- matvec partials: 4 j-rows x 48 k (12 LDS.128, 96 fma2) ---
            unsigned long long a0 = 0ull, a1 = 0ull, a2 = 0ull, a3 = 0ull;
            const ulonglong2* zq = reinterpret_cast<const ulonglong2*>(z + ks);
#pragma unroll
            for (int q = 0; q < 12; ++q) {
                const ulonglong2 v = zq[q];   // warp-uniform broadcast LDS.128
                a0 = fma2(wpk[0][2 * q], v.x, a0); a0 = fma2(wpk[0][2 * q + 1], v.y, a0);
                a1 = fma2(wpk[1][2 * q], v.x, a1); a1 = fma2(wpk[1][2 * q + 1], v.y, a1);
                a2 = fma2(wpk[2][2 * q], v.x, a2); a2 = fma2(wpk[2][2 * q + 1], v.y, a2);
                a3 = fma2(wpk[3][2 * q], v.x, a3); a3 = fma2(wpk[3][2 * q + 1], v.y, a3);
            }
            {
                float4 p;
                p.x = lo_f(a0) + hi_f(a0);
                p.y = lo_f(a1) + hi_f(a1);
                p.z = lo_f(a2) + hi_f(a2);
                p.w = lo_f(a3) + hi_f(a3);
                *reinterpret_cast<float4*>(ps + wg * HID + jbase) = p;
            }
            group_bar(gid);

            // --- reduce: thread rj owns output row rj (4 partials, depth-2 tree) ---
            const float q0 = ps[0 * HID + rj];
            const float q1 = ps[1 * HID + rj];
            const float q2 = ps[2 * HID + rj];
            const float q3 = ps[3 * HID + rj];
            const float s  = ((q0 + q1) + (q2 + q3)) + bias_r;

            const float hn = fast_tanh(s);
            out[tt * (BATCH * HID) + nb] = hn;

            const float zn = hn + STD_F * nz;    // noisy carried state
            z[rj] = zn;
            if (stX && (tt + 1) < T_STEPS)
                z[HID + rj] = xn;                // stage next x

            if (tt == T_STEPS - 1 && out_size > T_STEPS * BATCH * HID)
                out[T_STEPS * (BATCH * HID) + nb] = zn;   // h_last

            group_bar(gid);
        }
    }
}

extern "C" void kernel_launch(void* const* d_in, const int* in_sizes, int n_in,
                              void* d_out, int out_size) {
    const float* x         = (const float*)d_in[0];
    const float* w_ih      = (const float*)d_in[1];
    const float* w_hh      = (const float*)d_in[2];
    const float* b_ih      = (const float*)d_in[3];
    const float* b_hh      = (const float*)d_in[4];
    const float* noise     = (const float*)d_in[5];
    const float* hidden_in = (const float*)d_in[6];
    float* out = (float*)d_out;

    noise_rnn_kernel<<<BATCH / 2, THREADS>>>(x, w_ih, w_hh, b_ih, b_hh,
                                             noise, hidden_in, out, out_size);
}